// round 15
// baseline (speedup 1.0000x reference)
#include <cuda_runtime.h>
#include <math.h>

#define BB 4
#define SS 64
#define DD 512
#define HH 8
#define DH 64
#define DFF 2048
#define LL 2
#define VV 32128
#define TT 16
#define NBLK 128

// ---------------- scratch (device globals; 16B-aligned for float4 access) ----------
__device__ __align__(16) float g_x[BB*SS*DD];
__device__ __align__(16) float g_h[BB*SS*DD];
__device__ __align__(16) float g_qkv[3*BB*SS*DD];
__device__ __align__(16) float g_ao[BB*SS*DD];
__device__ __align__(16) float g_ffn[BB*SS*DFF];
__device__ __align__(16) float g_hs[BB*SS*DD];
__device__ __align__(16) float g_ckv[2*LL*BB*SS*DD];   // cross K|V per layer
__device__ __align__(16) float g_ksc[LL*BB*TT*DD];     // self K cache
__device__ __align__(16) float g_vsc[LL*BB*TT*DD];     // self V cache
__device__ __align__(16) float g_xb[2][BB*DD];         // ping-pong y buffers
__device__ __align__(16) float g_dx[BB*DD];
__device__ __align__(16) float g_dq[BB*DD];
__device__ __align__(16) float g_dffn[BB*DFF];
__device__ __align__(16) float g_logits[BB*VV];
__device__ __align__(16) float g_bias[BB*SS];
__device__ __align__(16) float g_red_sum[BB];
__device__ __align__(16) unsigned long long g_red_key[BB];

// ---------------- hierarchical grid barrier ----------------
// Arrival: 16 group counters (8 blocks each, separate 128B lines) -> 1 root (16).
// Worst-case atomic queue depth 8+16 instead of 128. Release: single broadcast
// line, plain spin (no nanosleep -- R12 showed sleep wakeup costs ~3us/barrier).
__device__ __align__(128) unsigned g_barL[16 * 32];       // [g*32] used
__device__ __align__(128) unsigned g_barRoot[32];         // [0] used
__device__ __align__(128) volatile unsigned g_barG[32];   // [0] used

__device__ __forceinline__ void gbar() {
    __syncthreads();
    if (threadIdx.x == 0) {
        unsigned gen = g_barG[0];
        __threadfence();
        int grp = blockIdx.x >> 3;  // 16 groups of 8
        if (atomicAdd(&g_barL[grp * 32], 1u) == 7u) {
            g_barL[grp * 32] = 0u;
            if (atomicAdd(&g_barRoot[0], 1u) == 15u) {
                g_barRoot[0] = 0u;
                __threadfence();
                g_barG[0] = gen + 1u;
            }
        }
        while (g_barG[0] == gen) { }
        __threadfence();
    }
    __syncthreads();
}

__device__ __forceinline__ float warpSum(float v) {
#pragma unroll
    for (int o = 16; o > 0; o >>= 1) v += __shfl_xor_sync(0xffffffffu, v, o);
    return v;
}

__device__ __forceinline__ void shfl4(float4& a, int o) {
    a.x += __shfl_down_sync(0xffffffffu, a.x, o);
    a.y += __shfl_down_sync(0xffffffffu, a.y, o);
    a.z += __shfl_down_sync(0xffffffffu, a.z, o);
    a.w += __shfl_down_sync(0xffffffffu, a.w, o);
}

__device__ __forceinline__ unsigned long long lkeyf(float v, int idx) {
    unsigned u = __float_as_uint(v);
    u = (u & 0x80000000u) ? ~u : (u | 0x80000000u);
    return (((unsigned long long)u) << 32) | (unsigned)(~idx);
}

// ---------------- embedding gather + encoder bias ----------------
__global__ void k_embed(const int* __restrict__ ids, const float* __restrict__ emb,
                        const float* __restrict__ mask) {
    int row = blockIdx.x;
    int id = ids[row];
    const float* e = emb + (size_t)id * DD;
    for (int d = threadIdx.x; d < DD; d += blockDim.x) g_x[row * DD + d] = e[d];
    if (threadIdx.x == 0) g_bias[row] = (1.0f - mask[row]) * -1e9f;
}

// ---------------- rmsnorm rows [M, DD] + fused buffer zeroing ----------------
__global__ void k_rmsnorm(const float* __restrict__ x, const float* __restrict__ w,
                          float* __restrict__ out, float* __restrict__ zbuf, int zn) {
    int row = blockIdx.x;
    const float* xr = x + (size_t)row * DD;
    float ss = 0.f;
    for (int i = threadIdx.x; i < DD; i += 256) { float v = xr[i]; ss += v * v; }
    ss = warpSum(ss);
    __shared__ float red[8];
    __shared__ float sscale;
    int lane = threadIdx.x & 31, wid = threadIdx.x >> 5;
    if (lane == 0) red[wid] = ss;
    __syncthreads();
    if (threadIdx.x == 0) {
        float s = 0.f;
        for (int i = 0; i < 8; i++) s += red[i];
        sscale = rsqrtf(s * (1.0f / DD) + 1e-6f);
    }
    __syncthreads();
    float sc = sscale;
    for (int i = threadIdx.x; i < DD; i += 256) out[(size_t)row * DD + i] = xr[i] * sc * w[i];
    if (zbuf) {
        int stride = gridDim.x * 256;
        for (int i = blockIdx.x * 256 + threadIdx.x; i < zn; i += stride) zbuf[i] = 0.f;
    }
}

// ---------------- encoder GEMM: split-K + multi-matrix fusion ----------------
__global__ void k_egemm3(const float* __restrict__ A,
                         const float* __restrict__ W0, const float* __restrict__ W1,
                         const float* __restrict__ W2,
                         float* __restrict__ C0, float* __restrict__ C1,
                         float* __restrict__ C2,
                         int N, int K, int KS, int reluA) {
    __shared__ __align__(16) float As[16][64];
    __shared__ __align__(16) float Ws[16][64];
    int zz = blockIdx.z;
    int mat = zz / KS, ks = zz - mat * KS;
    const float* W = (mat == 0) ? W0 : ((mat == 1) ? W1 : W2);
    float* C = (mat == 0) ? C0 : ((mat == 1) ? C1 : C2);
    int Kc = K / KS;
    int kbeg = ks * Kc;
    int tid = threadIdx.x;
    int tx = tid & 15, ty = tid >> 4;
    int bm = blockIdx.y * 64, bn = blockIdx.x * 64;
    int ar = tid >> 2, ac = (tid & 3) * 4;
    int wr = tid >> 4, wc = (tid & 15) * 4;
    float acc[4][4] = {};
    for (int k0 = kbeg; k0 < kbeg + Kc; k0 += 16) {
        float4 av = *(const float4*)(A + (size_t)(bm + ar) * K + k0 + ac);
        if (reluA) {
            av.x = fmaxf(av.x, 0.f); av.y = fmaxf(av.y, 0.f);
            av.z = fmaxf(av.z, 0.f); av.w = fmaxf(av.w, 0.f);
        }
        As[ac + 0][ar] = av.x; As[ac + 1][ar] = av.y; As[ac + 2][ar] = av.z; As[ac + 3][ar] = av.w;
        *(float4*)&Ws[wr][wc] = *(const float4*)(W + (size_t)(k0 + wr) * N + bn + wc);
        __syncthreads();
#pragma unroll
        for (int kk = 0; kk < 16; kk++) {
            float4 a = *(const float4*)&As[kk][ty * 4];
            float4 b = *(const float4*)&Ws[kk][tx * 4];
            acc[0][0] += a.x * b.x; acc[0][1] += a.x * b.y; acc[0][2] += a.x * b.z; acc[0][3] += a.x * b.w;
            acc[1][0] += a.y * b.x; acc[1][1] += a.y * b.y; acc[1][2] += a.y * b.z; acc[1][3] += a.y * b.w;
            acc[2][0] += a.z * b.x; acc[2][1] += a.z * b.y; acc[2][2] += a.z * b.z; acc[2][3] += a.z * b.w;
            acc[3][0] += a.w * b.x; acc[3][1] += a.w * b.y; acc[3][2] += a.w * b.z; acc[3][3] += a.w * b.w;
        }
        __syncthreads();
    }
#pragma unroll
    for (int i = 0; i < 4; i++) {
        int m = bm + ty * 4 + i;
#pragma unroll
        for (int j = 0; j < 4; j++)
            atomicAdd(&C[(size_t)m * N + bn + tx * 4 + j], acc[i][j]);
    }
}

// ---------------- encoder attention: 128 blocks (b,h,row-quarter) ----------------
__global__ __launch_bounds__(256) void k_enc_attn5(const float* __restrict__ q,
                                                   const float* __restrict__ k,
                                                   const float* __restrict__ v,
                                                   float* __restrict__ out) {
    __shared__ float qs[16 * 65];
    __shared__ float ks[64 * 65];
    int bh = blockIdx.x >> 2, quar = blockIdx.x & 3;
    int b = bh >> 3, h = bh & 7;
    int tid = threadIdx.x;
    size_t rowbase = ((size_t)b * SS) * DD + h * DH;
    {
        int r = tid >> 4, c4 = (tid & 15) << 2;
        float4 qv = *(const float4*)(q + rowbase + (size_t)(quar * 16 + r) * DD + c4);
        int base = r * 65 + c4;
        qs[base] = qv.x; qs[base + 1] = qv.y; qs[base + 2] = qv.z; qs[base + 3] = qv.w;
    }
    for (int x = tid; x < 1024; x += 256) {
        int r = x >> 4, c4 = (x & 15) << 2;
        float4 kv = *(const float4*)(k + rowbase + (size_t)r * DD + c4);
        int base = r * 65 + c4;
        ks[base] = kv.x; ks[base + 1] = kv.y; ks[base + 2] = kv.z; ks[base + 3] = kv.w;
    }
    __syncthreads();
    int i = tid >> 4, ph = tid & 15;
    float sc[4];
    const float* qrow = qs + i * 65;
#pragma unroll
    for (int jj = 0; jj < 4; jj++) {
        int j = jj * 16 + ph;
        const float* krow = ks + j * 65;
        float d = 0.f;
#pragma unroll
        for (int dd = 0; dd < 64; dd++) d += qrow[dd] * krow[dd];
        sc[jj] = d * 0.125f + g_bias[b * SS + j];
    }
    float m = -1e30f;
#pragma unroll
    for (int jj = 0; jj < 4; jj++) m = fmaxf(m, sc[jj]);
    m = fmaxf(m, __shfl_xor_sync(0xffffffffu, m, 1));
    m = fmaxf(m, __shfl_xor_sync(0xffffffffu, m, 2));
    m = fmaxf(m, __shfl_xor_sync(0xffffffffu, m, 4));
    m = fmaxf(m, __shfl_xor_sync(0xffffffffu, m, 8));
    float ssum = 0.f;
#pragma unroll
    for (int jj = 0; jj < 4; jj++) { sc[jj] = expf(sc[jj] - m); ssum += sc[jj]; }
    ssum += __shfl_xor_sync(0xffffffffu, ssum, 1);
    ssum += __shfl_xor_sync(0xffffffffu, ssum, 2);
    ssum += __shfl_xor_sync(0xffffffffu, ssum, 4);
    ssum += __shfl_xor_sync(0xffffffffu, ssum, 8);
    float inv = 1.f / ssum;
    __syncthreads();  // all QK reads complete
#pragma unroll
    for (int jj = 0; jj < 4; jj++) qs[i * 65 + jj * 16 + ph] = sc[jj] * inv;
    for (int x = tid; x < 1024; x += 256) {
        int r = x >> 4, c4 = (x & 15) << 2;
        float4 vv = *(const float4*)(v + rowbase + (size_t)r * DD + c4);
        int base = r * 65 + c4;
        ks[base] = vv.x; ks[base + 1] = vv.y; ks[base + 2] = vv.z; ks[base + 3] = vv.w;
    }
    __syncthreads();
    int d0 = ph * 4;
    float o0 = 0.f, o1 = 0.f, o2 = 0.f, o3 = 0.f;
    const float* prow = qs + i * 65;
    for (int j = 0; j < 64; j++) {
        float p = prow[j];
        const float* vrow = ks + j * 65 + d0;
        o0 += p * vrow[0]; o1 += p * vrow[1]; o2 += p * vrow[2]; o3 += p * vrow[3];
    }
    *(float4*)(out + rowbase + (size_t)(quar * 16 + i) * DD + d0) = make_float4(o0, o1, o2, o3);
}

// ---------------- decoder init ----------------
__global__ void k_dec_init(const float* __restrict__ emb) {
    int i = blockIdx.x * blockDim.x + threadIdx.x;
    if (i < BB * DD) { g_xb[0][i] = emb[i & (DD - 1)]; g_xb[1][i] = 0.f; }
    if (i < BB) { g_red_sum[i] = 0.f; g_red_key[i] = 0ull; }
}

// ---------------- fused rmsnorm (4 batch rows) into shared ----------------
__device__ __forceinline__ void load_norm(const float* __restrict__ x,
                                          const float* __restrict__ lnw,
                                          float* sh_h) {
    int tid = threadIdx.x;
    float ss[BB] = {0.f, 0.f, 0.f, 0.f};
    for (int i = tid; i < DD; i += 256) {
#pragma unroll
        for (int b = 0; b < BB; b++) {
            float v = x[b * DD + i];
            sh_h[b * DD + i] = v;
            ss[b] += v * v;
        }
    }
    __shared__ float sred[BB][8];
    __shared__ float sscale[BB];
    int lane = tid & 31, wid = tid >> 5;
#pragma unroll
    for (int b = 0; b < BB; b++) {
        float v = warpSum(ss[b]);
        if (lane == 0) sred[b][wid] = v;
    }
    __syncthreads();
    if (tid < BB) {
        float s = 0.f;
        for (int w = 0; w < 8; w++) s += sred[tid][w];
        sscale[tid] = rsqrtf(s * (1.0f / DD) + 1e-6f);
    }
    __syncthreads();
    for (int i = tid; i < DD; i += 256) {
        float w = lnw[i];
#pragma unroll
        for (int b = 0; b < BB; b++) sh_h[b * DD + i] *= sscale[b] * w;
    }
    __syncthreads();
}

// ---------------- vectorized in-block GEMV (R7-proven) ----------------
template<int COLG, int SPL, int KK>
__device__ __forceinline__ float4 dgemv4(const float* __restrict__ sh_a,
                                         const float* __restrict__ W, int ldw,
                                         int col0, float4* part) {
    int tid = threadIdx.x;
    int cg = tid % COLG, s = tid / COLG;
    constexpr int Kc = KK / SPL;
    const float* Wp = W + (size_t)(s * Kc) * ldw + col0 + cg * 4;
    const float* ap = sh_a + s * Kc;
    float4 a0 = make_float4(0.f, 0.f, 0.f, 0.f), a1 = a0, a2 = a0, a3 = a0;
#pragma unroll 8
    for (int i = 0; i < Kc; i++) {
        float4 w = *(const float4*)(Wp + (size_t)i * ldw);
        float x0 = ap[i], x1 = ap[KK + i], x2 = ap[2 * KK + i], x3 = ap[3 * KK + i];
        a0.x += x0 * w.x; a0.y += x0 * w.y; a0.z += x0 * w.z; a0.w += x0 * w.w;
        a1.x += x1 * w.x; a1.y += x1 * w.y; a1.z += x1 * w.z; a1.w += x1 * w.w;
        a2.x += x2 * w.x; a2.y += x2 * w.y; a2.z += x2 * w.z; a2.w += x2 * w.w;
        a3.x += x3 * w.x; a3.y += x3 * w.y; a3.z += x3 * w.z; a3.w += x3 * w.w;
    }
#pragma unroll
    for (int o = 16; o >= COLG; o >>= 1) {
        shfl4(a0, o); shfl4(a1, o); shfl4(a2, o); shfl4(a3, o);
    }
    int lane = tid & 31, w = tid >> 5;
    if (lane < COLG) {
        part[(w * COLG + lane) * 4 + 0] = a0;
        part[(w * COLG + lane) * 4 + 1] = a1;
        part[(w * COLG + lane) * 4 + 2] = a2;
        part[(w * COLG + lane) * 4 + 3] = a3;
    }
    __syncthreads();
    float4 r = make_float4(0.f, 0.f, 0.f, 0.f);
    if (tid < COLG * 4) {
        int c2 = tid % COLG, b2 = tid / COLG;
#pragma unroll
        for (int w2 = 0; w2 < 8; w2++) {
            float4 p = part[(w2 * COLG + c2) * 4 + b2];
            r.x += p.x; r.y += p.y; r.z += p.z; r.w += p.w;
        }
    }
    return r;
}

// ============================================================================
// DECODE MEGAKERNEL: 14 barriers/step.
// Per layer: S1 QKV(96blk) | S2 self-attn+o-scatter(32) | S4 cq(32)
//            | S5 cross-attn+co-scatter(32) | S7 ffn1(128) | S8 ffn2(64)
// ============================================================================
__global__ __launch_bounds__(256, 1) void k_decode(
    const float* __restrict__ dsq, const float* __restrict__ dsk,
    const float* __restrict__ dsv, const float* __restrict__ dso,
    const float* __restrict__ dln1,
    const float* __restrict__ dcq, const float* __restrict__ dco,
    const float* __restrict__ dln2,
    const float* __restrict__ dw1, const float* __restrict__ dw2,
    const float* __restrict__ dln3,
    const float* __restrict__ dlnf, const float* __restrict__ lmh,
    const float* __restrict__ emb,
    float* __restrict__ outp, float* __restrict__ outf) {
    __shared__ __align__(16) float sm[9216];
    int blk = blockIdx.x, tid = threadIdx.x;

    for (int t = 0; t < TT; t++) {
        float* cur = g_xb[t & 1];
        float* nxt = g_xb[(t + 1) & 1];
        for (int l = 0; l < LL; l++) {
            size_t o2 = (size_t)l * DD * DD;
            const float* Wsq = dsq + o2; const float* Wsk = dsk + o2;
            const float* Wsv = dsv + o2; const float* Wso = dso + o2;
            const float* Wcq = dcq + o2; const float* Wco = dco + o2;
            const float* Ww1 = dw1 + (size_t)l * DD * DFF;
            const float* Ww2 = dw2 + (size_t)l * DFF * DD;
            float* ksl = g_ksc + (size_t)l * BB * TT * DD;
            float* vsl = g_vsc + (size_t)l * BB * TT * DD;
            const float* kcl = g_ckv + (size_t)(l * 2 + 0) * BB * SS * DD;
            const float* vcl = g_ckv + (size_t)(l * 2 + 1) * BB * SS * DD;
            const float* xsrc = (l == 0) ? cur : g_dx;

            // S1: norm(ln1) + QKV gemv, KV-cache append (96 blocks, 16 cols each)
            if (blk < 96) {
                load_norm(xsrc, dln1 + l * DD, sm);
                int mat = blk >> 5, cb = blk & 31;
                const float* W = (mat == 0) ? Wsq : ((mat == 1) ? Wsk : Wsv);
                float4 r = dgemv4<4, 64, 512>(sm, W, DD, cb * 16, (float4*)(sm + 2048));
                if (tid < 16) {
                    int cg = tid & 3, b = tid >> 2;
                    int col = cb * 16 + cg * 4;
                    if (mat == 0) *(float4*)(g_dq + b * DD + col) = r;
                    else if (mat == 1) *(float4*)(ksl + ((size_t)b * TT + t) * DD + col) = r;
                    else *(float4*)(vsl + ((size_t)b * TT + t) * DD + col) = r;
                }
            } else if (blk == 127 && l == 0) {
                for (int i = tid; i < BB * DD; i += 256) g_dx[i] = cur[i];
            }
            gbar();

            // S2: self-attention + o-proj scatter into g_dx (32 blocks)
            if (blk < 32) {
                int b = blk >> 3, h = blk & 7;
                float* qs = sm; float* at = sm + 64; float* ex = sm + 128;
                float* ao = sm + 192;
                if (tid < 64) qs[tid] = g_dq[b * DD + h * DH + tid];
                __syncthreads();
                int nk = t + 1;
                if (tid < nk) {
                    const float* kr = ksl + ((size_t)b * TT + tid) * DD + h * DH;
                    float dot = 0.f;
#pragma unroll
                    for (int d = 0; d < DH; d++) dot += qs[d] * kr[d];
                    at[tid] = dot * 0.125f;
                }
                __syncthreads();
                float m = -1e30f;
                for (int j = 0; j < nk; j++) m = fmaxf(m, at[j]);
                if (tid < nk) ex[tid] = expf(at[tid] - m);
                __syncthreads();
                if (tid < 64) {
                    float s = 0.f;
                    for (int j = 0; j < nk; j++) s += ex[j];
                    const float* vb = vsl + (size_t)b * TT * DD + h * DH + tid;
                    float o = 0.f;
                    for (int j = 0; j < nk; j++) o += ex[j] * vb[(size_t)j * DD];
                    ao[tid] = o / s;
                }
                __syncthreads();
                // o-proj scatter: head h rows of Wso; residual already in g_dx
                float acc0 = 0.f, acc1 = 0.f;
                const float* wo = Wso + (size_t)(h * 64) * DD;
#pragma unroll 8
                for (int d = 0; d < 64; d++) {
                    float p = ao[d];
                    acc0 += p * wo[(size_t)d * DD + tid];
                    acc1 += p * wo[(size_t)d * DD + tid + 256];
                }
                atomicAdd(&g_dx[b * DD + tid], acc0);
                atomicAdd(&g_dx[b * DD + tid + 256], acc1);
            }
            gbar();

            // S4: norm(ln2) + cq gemv (32 blocks, 16 cols each)
            if (blk < 32) {
                load_norm(g_dx, dln2 + l * DD, sm);
                float4 r = dgemv4<4, 64, 512>(sm, Wcq, DD, blk * 16, (float4*)(sm + 2048));
                if (tid < 16) {
                    int cg = tid & 3, b = tid >> 2;
                    *(float4*)(g_dq + b * DD + blk * 16 + cg * 4) = r;
                }
            }
            gbar();

            // S5: cross-attention + co-proj scatter into g_dx (32 blocks)
            if (blk < 32) {
                int b = blk >> 3, h = blk & 7;
                float* qs = sm; float* at = sm + 64; float* ex = sm + 128;
                float* ao = sm + 192;
                if (tid < 64) qs[tid] = g_dq[b * DD + h * DH + tid];
                __syncthreads();
                if (tid < 64) {
                    const float* kr = kcl + ((size_t)b * SS + tid) * DD + h * DH;
                    float dot = 0.f;
#pragma unroll
                    for (int d = 0; d < DH; d++) dot += qs[d] * kr[d];
                    at[tid] = dot * 0.125f + g_bias[b * SS + tid];
                }
                __syncthreads();
                float m = -1e30f;
                for (int j = 0; j < SS; j++) m = fmaxf(m, at[j]);
                if (tid < 64) ex[tid] = expf(at[tid] - m);
                __syncthreads();
                if (tid < 64) {
                    float s = 0.f;
                    for (int j = 0; j < SS; j++) s += ex[j];
                    const float* vb = vcl + (size_t)b * SS * DD + h * DH + tid;
                    float o = 0.f;
                    for (int j = 0; j < SS; j++) o += ex[j] * vb[(size_t)j * DD];
                    ao[tid] = o / s;
                }
                __syncthreads();
                float acc0 = 0.f, acc1 = 0.f;
                const float* wo = Wco + (size_t)(h * 64) * DD;
#pragma unroll 8
                for (int d = 0; d < 64; d++) {
                    float p = ao[d];
                    acc0 += p * wo[(size_t)d * DD + tid];
                    acc1 += p * wo[(size_t)d * DD + tid + 256];
                }
                atomicAdd(&g_dx[b * DD + tid], acc0);
                atomicAdd(&g_dx[b * DD + tid + 256], acc1);
            }
            gbar();

            // S7: norm(ln3) + ffn1 + relu (128 blocks, 16 cols each)
            {
                load_norm(g_dx, dln3 + l * DD, sm);
                float4 r = dgemv4<4, 64, 512>(sm, Ww1, DFF, blk * 16, (float4*)(sm + 2048));
                if (tid < 16) {
                    int cg = tid & 3, b = tid >> 2;
                    r.x = fmaxf(r.x, 0.f); r.y = fmaxf(r.y, 0.f);
                    r.z = fmaxf(r.z, 0.f); r.w = fmaxf(r.w, 0.f);
                    *(float4*)(g_dffn + b * DFF + blk * 16 + cg * 4) = r;
                }
            }
            gbar();

            // S8: ffn2 + residual (64 blocks, 8 cols each); idle blocks prep buffers
            if (blk < 64) {
                float4* s4 = (float4*)sm;
                const float4* f4 = (const float4*)g_dffn;
#pragma unroll
                for (int i = 0; i < 8; i++) s4[i * 256 + tid] = f4[i * 256 + tid];
                __syncthreads();
                float4 r = dgemv4<2, 128, 2048>(sm, Ww2, DD, blk * 8, (float4*)(sm + 8192));
                if (tid < 8) {
                    int cg = tid & 1, b = tid >> 1;
                    int col = blk * 8 + cg * 4;
                    float4 x = *(float4*)(g_dx + b * DD + col);
                    x.x += r.x; x.y += r.y; x.z += r.z; x.w += r.w;
                    *(float4*)(g_dx + b * DD + col) = x;
                }
            } else if (l == 1 && blk == 64) {
                if (tid < BB) { g_red_sum[tid] = 0.f; g_red_key[tid] = 0ull; }
            } else if (l == 1 && blk == 65) {
                for (int i = tid; i < BB * DD; i += 256) cur[i] = 0.f;
            }
            gbar();
        }

        // S9: norm(lnf) + lm_head (__ldcs) + fused sumexp/argmax (128 blocks)
        load_norm(g_dx, dlnf, sm);
        {
            float4* part4 = (float4*)(sm + 2048);
            int g = tid & 31, s = tid >> 5;
            float lsum = 0.f;
            unsigned long long lkey = 0ull;
            for (int chunk = blk; chunk < 251; chunk += NBLK) {
                int col = chunk * 128 + (g << 2);
                float4 a0 = make_float4(0.f, 0.f, 0.f, 0.f), a1 = a0, a2 = a0, a3 = a0;
                const float* Wp = lmh + (size_t)(s * 64) * VV + col;
                const float* ap = sm + s * 64;
#pragma unroll 4
                for (int i = 0; i < 64; i++) {
                    float4 w = __ldcs((const float4*)(Wp + (size_t)i * VV));
                    float x0 = ap[i], x1 = ap[DD + i], x2 = ap[2 * DD + i], x3 = ap[3 * DD + i];
                    a0.x += x0 * w.x; a0.y += x0 * w.y; a0.z += x0 * w.z; a0.w += x0 * w.w;
                    a1.x += x1 * w.x; a1.y += x1 * w.y; a1.z += x1 * w.z; a1.w += x1 * w.w;
                    a2.x += x2 * w.x; a2.y += x2 * w.y; a2.z += x2 * w.z; a2.w += x2 * w.w;
                    a3.x += x3 * w.x; a3.y += x3 * w.y; a3.z += x3 * w.z; a3.w += x3 * w.w;
                }
                part4[tid * 4 + 0] = a0; part4[tid * 4 + 1] = a1;
                part4[tid * 4 + 2] = a2; part4[tid * 4 + 3] = a3;
                __syncthreads();
                if (tid < 128) {
                    int gg = tid & 31, b = tid >> 5;
                    float4 ts = make_float4(0.f, 0.f, 0.f, 0.f);
#pragma unroll
                    for (int s2 = 0; s2 < 8; s2++) {
                        float4 p = part4[(s2 * 32 + gg) * 4 + b];
                        ts.x += p.x; ts.y += p.y; ts.z += p.z; ts.w += p.w;
                    }
                    int cb = chunk * 128 + (gg << 2);
                    *(float4*)(g_logits + (size_t)b * VV + cb) = ts;
                    lsum += expf(ts.x) + expf(ts.y) + expf(ts.z) + expf(ts.w);
                    unsigned long long k0 = lkeyf(ts.x, cb);
                    unsigned long long k1 = lkeyf(ts.y, cb + 1);
                    unsigned long long k2 = lkeyf(ts.z, cb + 2);
                    unsigned long long k3 = lkeyf(ts.w, cb + 3);
                    if (k1 > k0) k0 = k1;
                    if (k3 > k2) k2 = k3;
                    if (k2 > k0) k0 = k2;
                    if (k0 > lkey) lkey = k0;
                }
                __syncthreads();
            }
            if (tid < 128) {
                float s2 = warpSum(lsum);
                unsigned long long kk = lkey;
#pragma unroll
                for (int o = 16; o > 0; o >>= 1) {
                    unsigned long long ot = __shfl_xor_sync(0xffffffffu, kk, o);
                    if (ot > kk) kk = ot;
                }
                if ((tid & 31) == 0) {
                    int b = tid >> 5;
                    atomicAdd(&g_red_sum[b], s2);
                    atomicMax(&g_red_key[b], kk);
                }
            }
        }
        gbar();

        // S11: probs write + pred flag + y_{t+1} = probs @ emb into nxt
        {
            float invb[BB];
#pragma unroll
            for (int b = 0; b < BB; b++) invb[b] = 1.f / g_red_sum[b];
            int colgrp = blk & 3, chunk = blk >> 2;  // 32 chunks * 1004 rows == VV
            int base = chunk * 1004;
            float* pp = sm;
            for (int i = tid; i < 1004; i += 256) {
#pragma unroll
                for (int b = 0; b < BB; b++) {
                    float pv = expf(g_logits[(size_t)b * VV + base + i]) * invb[b];
                    pp[b * 1004 + i] = pv;
                    if (colgrp == 0) __stcs(&outp[((size_t)b * TT + t) * VV + base + i], pv);
                }
            }
            __syncthreads();
            if (t + 1 < TT) {
                int g = tid & 31, s = tid >> 5;
                int col = (colgrp << 7) + (g << 2);
                float4 a0 = make_float4(0.f, 0.f, 0.f, 0.f), a1 = a0, a2 = a0, a3 = a0;
                for (int i = s; i < 1004; i += 8) {
                    float4 e = __ldcs((const float4*)(emb + (size_t)(base + i) * DD + col));
                    float p0 = pp[i], p1 = pp[1004 + i], p2 = pp[2008 + i], p3 = pp[3012 + i];
                    a0.x += p0 * e.x; a0.y += p0 * e.y; a0.z += p0 * e.z; a0.w += p0 * e.w;
                    a1.x += p1 * e.x; a1.y += p1 * e.y; a1.z += p1 * e.z; a1.w += p1 * e.w;
                    a2.x += p2 * e.x; a2.y += p2 * e.y; a2.z += p2 * e.z; a2.w += p2 * e.w;
                    a3.x += p3 * e.x; a3.y += p3 * e.y; a3.z += p3 * e.z; a3.w += p3 * e.w;
                }
                float4* part4 = (float4*)(sm + 4096);
                part4[tid * 4 + 0] = a0; part4[tid * 4 + 1] = a1;
                part4[tid * 4 + 2] = a2; part4[tid * 4 + 3] = a3;
                __syncthreads();
                if (tid < 128) {
                    int gg = tid & 31, b = tid >> 5;
                    float4 ts = make_float4(0.f, 0.f, 0.f, 0.f);
#pragma unroll
                    for (int s2 = 0; s2 < 8; s2++) {
                        float4 p = part4[(s2 * 32 + gg) * 4 + b];
                        ts.x += p.x; ts.y += p.y; ts.z += p.z; ts.w += p.w;
                    }
                    int co = (colgrp << 7) + (gg << 2);
                    atomicAdd(&nxt[b * DD + co + 0], ts.x);
                    atomicAdd(&nxt[b * DD + co + 1], ts.y);
                    atomicAdd(&nxt[b * DD + co + 2], ts.z);
                    atomicAdd(&nxt[b * DD + co + 3], ts.w);
                }
            }
            if (blk == 0 && tid < BB && outf) {
                unsigned idx = ~(unsigned)(g_red_key[tid] & 0xFFFFFFFFull);
                outf[tid * TT + t] = (idx == 0) ? 1.f : 0.f;
            }
        }
        gbar();
    }
}

// ============================================================================
extern "C" void kernel_launch(void* const* d_in, const int* in_sizes, int n_in,
                              void* d_out, int out_size) {
    const int*   ids  = (const int*)d_in[0];
    const float* mask = (const float*)d_in[1];
    const float* emb  = (const float*)d_in[2];
    const float* ewq  = (const float*)d_in[3];
    const float* ewk  = (const float*)d_in[4];
    const float* ewv  = (const float*)d_in[5];
    const float* ewo  = (const float*)d_in[6];
    const float* eln1 = (const float*)d_in[7];
    const float* ew1  = (const float*)d_in[8];
    const float* ew2  = (const float*)d_in[9];
    const float* eln2 = (const float*)d_in[10];
    const float* elnf = (const float*)d_in[11];
    const float* dsq  = (const float*)d_in[12];
    const float* dsk  = (const float*)d_in[13];
    const float* dsv  = (const float*)d_in[14];
    const float* dso  = (const float*)d_in[15];
    const float* dln1 = (const float*)d_in[16];
    const float* dcq  = (const float*)d_in[17];
    const float* dck  = (const float*)d_in[18];
    const float* dcv  = (const float*)d_in[19];
    const float* dco  = (const float*)d_in[20];
    const float* dln2 = (const float*)d_in[21];
    const float* dw1  = (const float*)d_in[22];
    const float* dw2  = (const float*)d_in[23];
    const float* dln3 = (const float*)d_in[24];
    const float* dlnf = (const float*)d_in[25];
    const float* lmh  = (const float*)d_in[26];

    float* outp = (float*)d_out;
    float* outf = (out_size >= BB * TT * VV + BB * TT) ? (outp + (size_t)BB * TT * VV) : nullptr;

    void* p;
    cudaGetSymbolAddress(&p, g_x);    float* px   = (float*)p;
    cudaGetSymbolAddress(&p, g_h);    float* ph   = (float*)p;
    cudaGetSymbolAddress(&p, g_qkv);  float* pqkv = (float*)p;
    cudaGetSymbolAddress(&p, g_ao);   float* pao  = (float*)p;
    cudaGetSymbolAddress(&p, g_ffn);  float* pffn = (float*)p;
    cudaGetSymbolAddress(&p, g_hs);   float* phs  = (float*)p;
    cudaGetSymbolAddress(&p, g_ckv);  float* pckv = (float*)p;

    const int M = BB * SS;   // 256
    const int MD = M * DD;   // 131072
    float* pq = pqkv;
    float* pk = pqkv + MD;
    float* pv = pqkv + 2 * MD;

    // ---------------- encoder ----------------
    k_embed<<<BB * SS, 128>>>(ids, emb, mask);
    for (int l = 0; l < LL; l++) {
        size_t o2 = (size_t)l * DD * DD;
        k_rmsnorm<<<M, 256>>>(px, eln1 + l * DD, ph, pqkv, 3 * MD);
        k_egemm3<<<dim3(8, 4, 6), 256>>>(ph, ewq + o2, ewk + o2, ewv + o2,
                                         pq, pk, pv, DD, DD, 2, 0);
        k_enc_attn5<<<BB * HH * 4, 256>>>(pq, pk, pv, pao);
        k_egemm3<<<dim3(8, 4, 4), 256>>>(pao, ewo + o2, nullptr, nullptr,
                                         px, nullptr, nullptr, DD, DD, 4, 0);
        k_rmsnorm<<<M, 256>>>(px, eln2 + l * DD, ph, pffn, M * DFF);
        k_egemm3<<<dim3(32, 4, 2), 256>>>(ph, ew1 + (size_t)l * DD * DFF, nullptr, nullptr,
                                          pffn, nullptr, nullptr, DFF, DD, 2, 0);
        k_egemm3<<<dim3(8, 4, 8), 256>>>(pffn, ew2 + (size_t)l * DFF * DD, nullptr, nullptr,
                                         px, nullptr, nullptr, DD, DFF, 8, 1);
    }
    k_rmsnorm<<<M, 256>>>(px, elnf, phs, pckv, 2 * LL * MD);
    for (int l = 0; l < LL; l++) {
        size_t o2 = (size_t)l * DD * DD;
        float* kcl = pckv + (size_t)(l * 2 + 0) * MD;
        float* vcl = pckv + (size_t)(l * 2 + 1) * MD;
        k_egemm3<<<dim3(8, 4, 4), 256>>>(phs, dck + o2, dcv + o2, nullptr,
                                         kcl, vcl, nullptr, DD, DD, 2, 0);
    }

    // ---------------- decoder: single persistent megakernel ----------------
    k_dec_init<<<(BB * DD + 255) / 256, 256>>>(emb);
    k_decode<<<NBLK, 256>>>(dsq, dsk, dsv, dso, dln1, dcq, dco, dln2,
                            dw1, dw2, dln3, dlnf, lmh, emb, outp, outf);
}

// round 16
// speedup vs baseline: 1.4794x; 1.4794x over previous
#include <cuda_runtime.h>
#include <math.h>

#define BB 4
#define SS 64
#define DD 512
#define HH 8
#define DH 64
#define DFF 2048
#define LL 2
#define VV 32128
#define TT 16
#define NBLK 128

// ---------------- scratch (device globals; 16B-aligned for float4 access) ----------
__device__ __align__(16) float g_x[BB*SS*DD];
__device__ __align__(16) float g_h[BB*SS*DD];
__device__ __align__(16) float g_qkv[3*BB*SS*DD];
__device__ __align__(16) float g_ao[BB*SS*DD];
__device__ __align__(16) float g_ffn[BB*SS*DFF];
__device__ __align__(16) float g_hs[BB*SS*DD];
__device__ __align__(16) float g_ckv[2*LL*BB*SS*DD];   // cross K|V per layer
__device__ __align__(16) float g_ksc[LL*BB*TT*DD];     // self K cache
__device__ __align__(16) float g_vsc[LL*BB*TT*DD];     // self V cache
__device__ __align__(16) float g_xb[2][BB*DD];         // ping-pong y buffers
__device__ __align__(16) float g_dx[BB*DD];
__device__ __align__(16) float g_dx2[BB*DD];           // post-cross residual stream
__device__ __align__(16) float g_dq[BB*DD];
__device__ __align__(16) float g_dffn[BB*DFF];
__device__ __align__(16) float g_logits[BB*VV];
__device__ __align__(16) float g_bias[BB*SS];
__device__ __align__(16) float g_red_sum[BB];
__device__ __align__(16) unsigned long long g_red_key[BB];

// ---------------- grid barrier (flat atomic — R11-proven optimum) ----------------
__device__ unsigned g_barA;
__device__ volatile unsigned g_barG;

__device__ __forceinline__ void gbar() {
    __syncthreads();
    if (threadIdx.x == 0) {
        unsigned gen = g_barG;
        __threadfence();
        if (atomicAdd(&g_barA, 1u) == NBLK - 1u) {
            g_barA = 0u;
            __threadfence();
            g_barG = gen + 1u;
        } else {
            while (g_barG == gen) { }
        }
        __threadfence();
    }
    __syncthreads();
}

__device__ __forceinline__ float warpSum(float v) {
#pragma unroll
    for (int o = 16; o > 0; o >>= 1) v += __shfl_xor_sync(0xffffffffu, v, o);
    return v;
}

__device__ __forceinline__ void shfl4(float4& a, int o) {
    a.x += __shfl_down_sync(0xffffffffu, a.x, o);
    a.y += __shfl_down_sync(0xffffffffu, a.y, o);
    a.z += __shfl_down_sync(0xffffffffu, a.z, o);
    a.w += __shfl_down_sync(0xffffffffu, a.w, o);
}

__device__ __forceinline__ unsigned long long lkeyf(float v, int idx) {
    unsigned u = __float_as_uint(v);
    u = (u & 0x80000000u) ? ~u : (u | 0x80000000u);
    return (((unsigned long long)u) << 32) | (unsigned)(~idx);
}

// ---------------- embedding gather + encoder bias ----------------
__global__ void k_embed(const int* __restrict__ ids, const float* __restrict__ emb,
                        const float* __restrict__ mask) {
    int row = blockIdx.x;
    int id = ids[row];
    const float* e = emb + (size_t)id * DD;
    for (int d = threadIdx.x; d < DD; d += blockDim.x) g_x[row * DD + d] = e[d];
    if (threadIdx.x == 0) g_bias[row] = (1.0f - mask[row]) * -1e9f;
}

// ---------------- rmsnorm rows [M, DD] + fused buffer zeroing ----------------
__global__ void k_rmsnorm(const float* __restrict__ x, const float* __restrict__ w,
                          float* __restrict__ out, float* __restrict__ zbuf, int zn) {
    int row = blockIdx.x;
    const float* xr = x + (size_t)row * DD;
    float ss = 0.f;
    for (int i = threadIdx.x; i < DD; i += 256) { float v = xr[i]; ss += v * v; }
    ss = warpSum(ss);
    __shared__ float red[8];
    __shared__ float sscale;
    int lane = threadIdx.x & 31, wid = threadIdx.x >> 5;
    if (lane == 0) red[wid] = ss;
    __syncthreads();
    if (threadIdx.x == 0) {
        float s = 0.f;
        for (int i = 0; i < 8; i++) s += red[i];
        sscale = rsqrtf(s * (1.0f / DD) + 1e-6f);
    }
    __syncthreads();
    float sc = sscale;
    for (int i = threadIdx.x; i < DD; i += 256) out[(size_t)row * DD + i] = xr[i] * sc * w[i];
    if (zbuf) {
        int stride = gridDim.x * 256;
        for (int i = blockIdx.x * 256 + threadIdx.x; i < zn; i += stride) zbuf[i] = 0.f;
    }
}

// ---------------- encoder GEMM: split-K + multi-matrix fusion ----------------
__global__ void k_egemm3(const float* __restrict__ A,
                         const float* __restrict__ W0, const float* __restrict__ W1,
                         const float* __restrict__ W2,
                         float* __restrict__ C0, float* __restrict__ C1,
                         float* __restrict__ C2,
                         int N, int K, int KS, int reluA) {
    __shared__ __align__(16) float As[16][64];
    __shared__ __align__(16) float Ws[16][64];
    int zz = blockIdx.z;
    int mat = zz / KS, ks = zz - mat * KS;
    const float* W = (mat == 0) ? W0 : ((mat == 1) ? W1 : W2);
    float* C = (mat == 0) ? C0 : ((mat == 1) ? C1 : C2);
    int Kc = K / KS;
    int kbeg = ks * Kc;
    int tid = threadIdx.x;
    int tx = tid & 15, ty = tid >> 4;
    int bm = blockIdx.y * 64, bn = blockIdx.x * 64;
    int ar = tid >> 2, ac = (tid & 3) * 4;
    int wr = tid >> 4, wc = (tid & 15) * 4;
    float acc[4][4] = {};
    for (int k0 = kbeg; k0 < kbeg + Kc; k0 += 16) {
        float4 av = *(const float4*)(A + (size_t)(bm + ar) * K + k0 + ac);
        if (reluA) {
            av.x = fmaxf(av.x, 0.f); av.y = fmaxf(av.y, 0.f);
            av.z = fmaxf(av.z, 0.f); av.w = fmaxf(av.w, 0.f);
        }
        As[ac + 0][ar] = av.x; As[ac + 1][ar] = av.y; As[ac + 2][ar] = av.z; As[ac + 3][ar] = av.w;
        *(float4*)&Ws[wr][wc] = *(const float4*)(W + (size_t)(k0 + wr) * N + bn + wc);
        __syncthreads();
#pragma unroll
        for (int kk = 0; kk < 16; kk++) {
            float4 a = *(const float4*)&As[kk][ty * 4];
            float4 b = *(const float4*)&Ws[kk][tx * 4];
            acc[0][0] += a.x * b.x; acc[0][1] += a.x * b.y; acc[0][2] += a.x * b.z; acc[0][3] += a.x * b.w;
            acc[1][0] += a.y * b.x; acc[1][1] += a.y * b.y; acc[1][2] += a.y * b.z; acc[1][3] += a.y * b.w;
            acc[2][0] += a.z * b.x; acc[2][1] += a.z * b.y; acc[2][2] += a.z * b.z; acc[2][3] += a.z * b.w;
            acc[3][0] += a.w * b.x; acc[3][1] += a.w * b.y; acc[3][2] += a.w * b.z; acc[3][3] += a.w * b.w;
        }
        __syncthreads();
    }
#pragma unroll
    for (int i = 0; i < 4; i++) {
        int m = bm + ty * 4 + i;
#pragma unroll
        for (int j = 0; j < 4; j++)
            atomicAdd(&C[(size_t)m * N + bn + tx * 4 + j], acc[i][j]);
    }
}

// ---------------- encoder attention: 128 blocks (b,h,row-quarter) ----------------
__global__ __launch_bounds__(256) void k_enc_attn5(const float* __restrict__ q,
                                                   const float* __restrict__ k,
                                                   const float* __restrict__ v,
                                                   float* __restrict__ out) {
    __shared__ float qs[16 * 65];
    __shared__ float ks[64 * 65];
    int bh = blockIdx.x >> 2, quar = blockIdx.x & 3;
    int b = bh >> 3, h = bh & 7;
    int tid = threadIdx.x;
    size_t rowbase = ((size_t)b * SS) * DD + h * DH;
    {
        int r = tid >> 4, c4 = (tid & 15) << 2;
        float4 qv = *(const float4*)(q + rowbase + (size_t)(quar * 16 + r) * DD + c4);
        int base = r * 65 + c4;
        qs[base] = qv.x; qs[base + 1] = qv.y; qs[base + 2] = qv.z; qs[base + 3] = qv.w;
    }
    for (int x = tid; x < 1024; x += 256) {
        int r = x >> 4, c4 = (x & 15) << 2;
        float4 kv = *(const float4*)(k + rowbase + (size_t)r * DD + c4);
        int base = r * 65 + c4;
        ks[base] = kv.x; ks[base + 1] = kv.y; ks[base + 2] = kv.z; ks[base + 3] = kv.w;
    }
    __syncthreads();
    int i = tid >> 4, ph = tid & 15;
    float sc[4];
    const float* qrow = qs + i * 65;
#pragma unroll
    for (int jj = 0; jj < 4; jj++) {
        int j = jj * 16 + ph;
        const float* krow = ks + j * 65;
        float d = 0.f;
#pragma unroll
        for (int dd = 0; dd < 64; dd++) d += qrow[dd] * krow[dd];
        sc[jj] = d * 0.125f + g_bias[b * SS + j];
    }
    float m = -1e30f;
#pragma unroll
    for (int jj = 0; jj < 4; jj++) m = fmaxf(m, sc[jj]);
    m = fmaxf(m, __shfl_xor_sync(0xffffffffu, m, 1));
    m = fmaxf(m, __shfl_xor_sync(0xffffffffu, m, 2));
    m = fmaxf(m, __shfl_xor_sync(0xffffffffu, m, 4));
    m = fmaxf(m, __shfl_xor_sync(0xffffffffu, m, 8));
    float ssum = 0.f;
#pragma unroll
    for (int jj = 0; jj < 4; jj++) { sc[jj] = expf(sc[jj] - m); ssum += sc[jj]; }
    ssum += __shfl_xor_sync(0xffffffffu, ssum, 1);
    ssum += __shfl_xor_sync(0xffffffffu, ssum, 2);
    ssum += __shfl_xor_sync(0xffffffffu, ssum, 4);
    ssum += __shfl_xor_sync(0xffffffffu, ssum, 8);
    float inv = 1.f / ssum;
    __syncthreads();  // all QK reads complete
#pragma unroll
    for (int jj = 0; jj < 4; jj++) qs[i * 65 + jj * 16 + ph] = sc[jj] * inv;
    for (int x = tid; x < 1024; x += 256) {
        int r = x >> 4, c4 = (x & 15) << 2;
        float4 vv = *(const float4*)(v + rowbase + (size_t)r * DD + c4);
        int base = r * 65 + c4;
        ks[base] = vv.x; ks[base + 1] = vv.y; ks[base + 2] = vv.z; ks[base + 3] = vv.w;
    }
    __syncthreads();
    int d0 = ph * 4;
    float o0 = 0.f, o1 = 0.f, o2 = 0.f, o3 = 0.f;
    const float* prow = qs + i * 65;
    for (int j = 0; j < 64; j++) {
        float p = prow[j];
        const float* vrow = ks + j * 65 + d0;
        o0 += p * vrow[0]; o1 += p * vrow[1]; o2 += p * vrow[2]; o3 += p * vrow[3];
    }
    *(float4*)(out + rowbase + (size_t)(quar * 16 + i) * DD + d0) = make_float4(o0, o1, o2, o3);
}

// ---------------- decoder init ----------------
__global__ void k_dec_init(const float* __restrict__ emb) {
    int i = blockIdx.x * blockDim.x + threadIdx.x;
    if (i < BB * DD) { g_xb[0][i] = emb[i & (DD - 1)]; g_xb[1][i] = 0.f; }
    if (i < BB) { g_red_sum[i] = 0.f; g_red_key[i] = 0ull; }
}

// ---------------- fused rmsnorm (4 batch rows) into shared ----------------
__device__ __forceinline__ void load_norm(const float* __restrict__ x,
                                          const float* __restrict__ lnw,
                                          float* sh_h) {
    int tid = threadIdx.x;
    float ss[BB] = {0.f, 0.f, 0.f, 0.f};
    for (int i = tid; i < DD; i += 256) {
#pragma unroll
        for (int b = 0; b < BB; b++) {
            float v = x[b * DD + i];
            sh_h[b * DD + i] = v;
            ss[b] += v * v;
        }
    }
    __shared__ float sred[BB][8];
    __shared__ float sscale[BB];
    int lane = tid & 31, wid = tid >> 5;
#pragma unroll
    for (int b = 0; b < BB; b++) {
        float v = warpSum(ss[b]);
        if (lane == 0) sred[b][wid] = v;
    }
    __syncthreads();
    if (tid < BB) {
        float s = 0.f;
        for (int w = 0; w < 8; w++) s += sred[tid][w];
        sscale[tid] = rsqrtf(s * (1.0f / DD) + 1e-6f);
    }
    __syncthreads();
    for (int i = tid; i < DD; i += 256) {
        float w = lnw[i];
#pragma unroll
        for (int b = 0; b < BB; b++) sh_h[b * DD + i] *= sscale[b] * w;
    }
    __syncthreads();
}

// ---------------- single-row rmsnorm into shared xs + raw copy xraw -----------------
__device__ __forceinline__ void norm_row(const float* __restrict__ xrow,
                                         const float* __restrict__ lnw,
                                         float* xs, float* xraw) {
    int tid = threadIdx.x;
    __shared__ float nred[8];
    __shared__ float nscale;
    float a = xrow[tid], b2 = xrow[tid + 256];
    xraw[tid] = a; xraw[tid + 256] = b2;
    float v = warpSum(a * a + b2 * b2);
    if ((tid & 31) == 0) nred[tid >> 5] = v;
    __syncthreads();
    if (tid == 0) {
        float s = 0.f;
        for (int w = 0; w < 8; w++) s += nred[w];
        nscale = rsqrtf(s * (1.0f / DD) + 1e-6f);
    }
    __syncthreads();
    float sc = nscale;
    xs[tid] = a * sc * lnw[tid];
    xs[tid + 256] = b2 * sc * lnw[tid + 256];
    __syncthreads();
}

// ---------------- vectorized in-block GEMV (R7-proven) ----------------
template<int COLG, int SPL, int KK>
__device__ __forceinline__ float4 dgemv4(const float* __restrict__ sh_a,
                                         const float* __restrict__ W, int ldw,
                                         int col0, float4* part) {
    int tid = threadIdx.x;
    int cg = tid % COLG, s = tid / COLG;
    constexpr int Kc = KK / SPL;
    const float* Wp = W + (size_t)(s * Kc) * ldw + col0 + cg * 4;
    const float* ap = sh_a + s * Kc;
    float4 a0 = make_float4(0.f, 0.f, 0.f, 0.f), a1 = a0, a2 = a0, a3 = a0;
#pragma unroll 8
    for (int i = 0; i < Kc; i++) {
        float4 w = *(const float4*)(Wp + (size_t)i * ldw);
        float x0 = ap[i], x1 = ap[KK + i], x2 = ap[2 * KK + i], x3 = ap[3 * KK + i];
        a0.x += x0 * w.x; a0.y += x0 * w.y; a0.z += x0 * w.z; a0.w += x0 * w.w;
        a1.x += x1 * w.x; a1.y += x1 * w.y; a1.z += x1 * w.z; a1.w += x1 * w.w;
        a2.x += x2 * w.x; a2.y += x2 * w.y; a2.z += x2 * w.z; a2.w += x2 * w.w;
        a3.x += x3 * w.x; a3.y += x3 * w.y; a3.z += x3 * w.z; a3.w += x3 * w.w;
    }
#pragma unroll
    for (int o = 16; o >= COLG; o >>= 1) {
        shfl4(a0, o); shfl4(a1, o); shfl4(a2, o); shfl4(a3, o);
    }
    int lane = tid & 31, w = tid >> 5;
    if (lane < COLG) {
        part[(w * COLG + lane) * 4 + 0] = a0;
        part[(w * COLG + lane) * 4 + 1] = a1;
        part[(w * COLG + lane) * 4 + 2] = a2;
        part[(w * COLG + lane) * 4 + 3] = a3;
    }
    __syncthreads();
    float4 r = make_float4(0.f, 0.f, 0.f, 0.f);
    if (tid < COLG * 4) {
        int c2 = tid % COLG, b2 = tid / COLG;
#pragma unroll
        for (int w2 = 0; w2 < 8; w2++) {
            float4 p = part[(w2 * COLG + c2) * 4 + b2];
            r.x += p.x; r.y += p.y; r.z += p.z; r.w += p.w;
        }
    }
    return r;
}

// ============================================================================
// DECODE MEGAKERNEL: 12 barriers/step.
// Per layer: S1 QKV(96blk) | S2 self-attn+o-scatter->g_dx (32; idle zero g_dx2)
//            | S5 norm+cq(head)+cross-attn+co-scatter->g_dx2 (32)
//            | S7 ffn1 from g_dx2 (128) | S8 ffn2: g_dx = g_dx2 + out (64)
// ============================================================================
__global__ __launch_bounds__(256, 1) void k_decode(
    const float* __restrict__ dsq, const float* __restrict__ dsk,
    const float* __restrict__ dsv, const float* __restrict__ dso,
    const float* __restrict__ dln1,
    const float* __restrict__ dcq, const float* __restrict__ dco,
    const float* __restrict__ dln2,
    const float* __restrict__ dw1, const float* __restrict__ dw2,
    const float* __restrict__ dln3,
    const float* __restrict__ dlnf, const float* __restrict__ lmh,
    const float* __restrict__ emb,
    float* __restrict__ outp, float* __restrict__ outf) {
    __shared__ __align__(16) float sm[9216];
    int blk = blockIdx.x, tid = threadIdx.x;

    for (int t = 0; t < TT; t++) {
        float* cur = g_xb[t & 1];
        float* nxt = g_xb[(t + 1) & 1];
        for (int l = 0; l < LL; l++) {
            size_t o2 = (size_t)l * DD * DD;
            const float* Wsq = dsq + o2; const float* Wsk = dsk + o2;
            const float* Wsv = dsv + o2; const float* Wso = dso + o2;
            const float* Wcq = dcq + o2; const float* Wco = dco + o2;
            const float* Ww1 = dw1 + (size_t)l * DD * DFF;
            const float* Ww2 = dw2 + (size_t)l * DFF * DD;
            float* ksl = g_ksc + (size_t)l * BB * TT * DD;
            float* vsl = g_vsc + (size_t)l * BB * TT * DD;
            const float* kcl = g_ckv + (size_t)(l * 2 + 0) * BB * SS * DD;
            const float* vcl = g_ckv + (size_t)(l * 2 + 1) * BB * SS * DD;
            const float* xsrc = (l == 0) ? cur : g_dx;

            // S1: norm(ln1) + QKV gemv, KV-cache append (96 blocks, 16 cols each)
            if (blk < 96) {
                load_norm(xsrc, dln1 + l * DD, sm);
                int mat = blk >> 5, cb = blk & 31;
                const float* W = (mat == 0) ? Wsq : ((mat == 1) ? Wsk : Wsv);
                float4 r = dgemv4<4, 64, 512>(sm, W, DD, cb * 16, (float4*)(sm + 2048));
                if (tid < 16) {
                    int cg = tid & 3, b = tid >> 2;
                    int col = cb * 16 + cg * 4;
                    if (mat == 0) *(float4*)(g_dq + b * DD + col) = r;
                    else if (mat == 1) *(float4*)(ksl + ((size_t)b * TT + t) * DD + col) = r;
                    else *(float4*)(vsl + ((size_t)b * TT + t) * DD + col) = r;
                }
            } else if (blk == 127 && l == 0) {
                for (int i = tid; i < BB * DD; i += 256) g_dx[i] = cur[i];
            }
            gbar();

            // S2: self-attention + o-proj scatter into g_dx (32 blocks);
            //     idle block 32 zeroes g_dx2 for S5's scatter.
            if (blk < 32) {
                int b = blk >> 3, h = blk & 7;
                float* qs = sm; float* at = sm + 64; float* ex = sm + 128;
                float* ao = sm + 192;
                if (tid < 64) qs[tid] = g_dq[b * DD + h * DH + tid];
                __syncthreads();
                int nk = t + 1;
                if (tid < nk) {
                    const float* kr = ksl + ((size_t)b * TT + tid) * DD + h * DH;
                    float dot = 0.f;
#pragma unroll
                    for (int d = 0; d < DH; d++) dot += qs[d] * kr[d];
                    at[tid] = dot * 0.125f;
                }
                __syncthreads();
                float m = -1e30f;
                for (int j = 0; j < nk; j++) m = fmaxf(m, at[j]);
                if (tid < nk) ex[tid] = expf(at[tid] - m);
                __syncthreads();
                if (tid < 64) {
                    float s = 0.f;
                    for (int j = 0; j < nk; j++) s += ex[j];
                    const float* vb = vsl + (size_t)b * TT * DD + h * DH + tid;
                    float o = 0.f;
                    for (int j = 0; j < nk; j++) o += ex[j] * vb[(size_t)j * DD];
                    ao[tid] = o / s;
                }
                __syncthreads();
                float acc0 = 0.f, acc1 = 0.f;
                const float* wo = Wso + (size_t)(h * 64) * DD;
#pragma unroll 8
                for (int d = 0; d < 64; d++) {
                    float p = ao[d];
                    acc0 += p * wo[(size_t)d * DD + tid];
                    acc1 += p * wo[(size_t)d * DD + tid + 256];
                }
                atomicAdd(&g_dx[b * DD + tid], acc0);
                atomicAdd(&g_dx[b * DD + tid + 256], acc1);
            } else if (blk == 32) {
                for (int i = tid; i < BB * DD; i += 256) g_dx2[i] = 0.f;
            }
            gbar();

            // S5: norm(ln2) + per-head cq gemv + cross-attn + co scatter -> g_dx2
            //     (32 blocks; reads g_dx, writes ONLY g_dx2 -> no read/write race).
            if (blk < 32) {
                int b = blk >> 3, h = blk & 7;
                float* xs = sm;
                float* xraw = sm + 512;
                float4* red = (float4*)(sm + 1024);   // 128 float4
                float* qs = sm + 2560;
                float* at = sm + 2624;
                float* esm = sm + 2688;
                float* ao = sm + 2752;
                norm_row(g_dx + b * DD, dln2 + l * DD, xs, xraw);
                {
                    int cg = tid & 15, s = tid >> 4;
                    const float* wq = Wcq + (size_t)(s * 32) * DD + h * 64 + cg * 4;
                    const float* xp = xs + s * 32;
                    float4 aq = make_float4(0.f, 0.f, 0.f, 0.f);
#pragma unroll 8
                    for (int i = 0; i < 32; i++) {
                        float xv = xp[i];
                        float4 w = *(const float4*)(wq + (size_t)i * DD);
                        aq.x += xv * w.x; aq.y += xv * w.y; aq.z += xv * w.z; aq.w += xv * w.w;
                    }
                    shfl4(aq, 16);
                    int lane = tid & 31, w2 = tid >> 5;
                    if (lane < 16) red[w2 * 16 + lane] = aq;
                }
                __syncthreads();
                if (tid < 16) {
                    float4 r = make_float4(0.f, 0.f, 0.f, 0.f);
#pragma unroll
                    for (int w2 = 0; w2 < 8; w2++) {
                        float4 p = red[w2 * 16 + tid];
                        r.x += p.x; r.y += p.y; r.z += p.z; r.w += p.w;
                    }
                    qs[tid * 4] = r.x; qs[tid * 4 + 1] = r.y;
                    qs[tid * 4 + 2] = r.z; qs[tid * 4 + 3] = r.w;
                }
                __syncthreads();
                if (tid < 64) {
                    const float* kr = kcl + ((size_t)b * SS + tid) * DD + h * 64;
                    float d = 0.f;
#pragma unroll
                    for (int dd = 0; dd < 64; dd++) d += qs[dd] * kr[dd];
                    at[tid] = d * 0.125f + g_bias[b * SS + tid];
                }
                __syncthreads();
                if (tid < 64) {
                    float m = -1e30f;
                    for (int j = 0; j < 64; j++) m = fmaxf(m, at[j]);
                    esm[tid] = expf(at[tid] - m);
                }
                __syncthreads();
                if (tid < 64) {
                    float s2 = 0.f;
                    for (int j = 0; j < 64; j++) s2 += esm[j];
                    float o = 0.f;
                    const float* vb = vcl + (size_t)b * SS * DD + h * 64 + tid;
                    for (int j = 0; j < 64; j++) o += esm[j] * vb[(size_t)j * DD];
                    ao[tid] = o / s2;
                }
                __syncthreads();
                float acc0 = 0.f, acc1 = 0.f;
                const float* wo = Wco + (size_t)(h * 64) * DD;
#pragma unroll 8
                for (int d = 0; d < 64; d++) {
                    float p = ao[d];
                    acc0 += p * wo[(size_t)d * DD + tid];
                    acc1 += p * wo[(size_t)d * DD + tid + 256];
                }
                if (h == 0) { acc0 += xraw[tid]; acc1 += xraw[tid + 256]; }
                atomicAdd(&g_dx2[b * DD + tid], acc0);
                atomicAdd(&g_dx2[b * DD + tid + 256], acc1);
            }
            gbar();

            // S7: norm(ln3) on g_dx2 + ffn1 + relu (128 blocks, 16 cols each)
            {
                load_norm(g_dx2, dln3 + l * DD, sm);
                float4 r = dgemv4<4, 64, 512>(sm, Ww1, DFF, blk * 16, (float4*)(sm + 2048));
                if (tid < 16) {
                    int cg = tid & 3, b = tid >> 2;
                    r.x = fmaxf(r.x, 0.f); r.y = fmaxf(r.y, 0.f);
                    r.z = fmaxf(r.z, 0.f); r.w = fmaxf(r.w, 0.f);
                    *(float4*)(g_dffn + b * DFF + blk * 16 + cg * 4) = r;
                }
            }
            gbar();

            // S8: ffn2: g_dx = g_dx2 + out (64 blocks); idle blocks prep buffers
            if (blk < 64) {
                float4* s4 = (float4*)sm;
                const float4* f4 = (const float4*)g_dffn;
#pragma unroll
                for (int i = 0; i < 8; i++) s4[i * 256 + tid] = f4[i * 256 + tid];
                __syncthreads();
                float4 r = dgemv4<2, 128, 2048>(sm, Ww2, DD, blk * 8, (float4*)(sm + 8192));
                if (tid < 8) {
                    int cg = tid & 1, b = tid >> 1;
                    int col = blk * 8 + cg * 4;
                    float4 x = *(float4*)(g_dx2 + b * DD + col);
                    x.x += r.x; x.y += r.y; x.z += r.z; x.w += r.w;
                    *(float4*)(g_dx + b * DD + col) = x;
                }
            } else if (l == 1 && blk == 64) {
                if (tid < BB) { g_red_sum[tid] = 0.f; g_red_key[tid] = 0ull; }
            } else if (l == 1 && blk == 65) {
                for (int i = tid; i < BB * DD; i += 256) cur[i] = 0.f;
            }
            gbar();
        }

        // S9: norm(lnf) + lm_head (__ldcs) + fused sumexp/argmax (128 blocks)
        load_norm(g_dx, dlnf, sm);
        {
            float4* part4 = (float4*)(sm + 2048);
            int g = tid & 31, s = tid >> 5;
            float lsum = 0.f;
            unsigned long long lkey = 0ull;
            for (int chunk = blk; chunk < 251; chunk += NBLK) {
                int col = chunk * 128 + (g << 2);
                float4 a0 = make_float4(0.f, 0.f, 0.f, 0.f), a1 = a0, a2 = a0, a3 = a0;
                const float* Wp = lmh + (size_t)(s * 64) * VV + col;
                const float* ap = sm + s * 64;
#pragma unroll 4
                for (int i = 0; i < 64; i++) {
                    float4 w = __ldcs((const float4*)(Wp + (size_t)i * VV));
                    float x0 = ap[i], x1 = ap[DD + i], x2 = ap[2 * DD + i], x3 = ap[3 * DD + i];
                    a0.x += x0 * w.x; a0.y += x0 * w.y; a0.z += x0 * w.z; a0.w += x0 * w.w;
                    a1.x += x1 * w.x; a1.y += x1 * w.y; a1.z += x1 * w.z; a1.w += x1 * w.w;
                    a2.x += x2 * w.x; a2.y += x2 * w.y; a2.z += x2 * w.z; a2.w += x2 * w.w;
                    a3.x += x3 * w.x; a3.y += x3 * w.y; a3.z += x3 * w.z; a3.w += x3 * w.w;
                }
                part4[tid * 4 + 0] = a0; part4[tid * 4 + 1] = a1;
                part4[tid * 4 + 2] = a2; part4[tid * 4 + 3] = a3;
                __syncthreads();
                if (tid < 128) {
                    int gg = tid & 31, b = tid >> 5;
                    float4 ts = make_float4(0.f, 0.f, 0.f, 0.f);
#pragma unroll
                    for (int s2 = 0; s2 < 8; s2++) {
                        float4 p = part4[(s2 * 32 + gg) * 4 + b];
                        ts.x += p.x; ts.y += p.y; ts.z += p.z; ts.w += p.w;
                    }
                    int cb = chunk * 128 + (gg << 2);
                    *(float4*)(g_logits + (size_t)b * VV + cb) = ts;
                    lsum += expf(ts.x) + expf(ts.y) + expf(ts.z) + expf(ts.w);
                    unsigned long long k0 = lkeyf(ts.x, cb);
                    unsigned long long k1 = lkeyf(ts.y, cb + 1);
                    unsigned long long k2 = lkeyf(ts.z, cb + 2);
                    unsigned long long k3 = lkeyf(ts.w, cb + 3);
                    if (k1 > k0) k0 = k1;
                    if (k3 > k2) k2 = k3;
                    if (k2 > k0) k0 = k2;
                    if (k0 > lkey) lkey = k0;
                }
                __syncthreads();
            }
            if (tid < 128) {
                float s2 = warpSum(lsum);
                unsigned long long kk = lkey;
#pragma unroll
                for (int o = 16; o > 0; o >>= 1) {
                    unsigned long long ot = __shfl_xor_sync(0xffffffffu, kk, o);
                    if (ot > kk) kk = ot;
                }
                if ((tid & 31) == 0) {
                    int b = tid >> 5;
                    atomicAdd(&g_red_sum[b], s2);
                    atomicMax(&g_red_key[b], kk);
                }
            }
        }
        gbar();

        // S11: probs write + pred flag + y_{t+1} = probs @ emb into nxt
        {
            float invb[BB];
#pragma unroll
            for (int b = 0; b < BB; b++) invb[b] = 1.f / g_red_sum[b];
            int colgrp = blk & 3, chunk = blk >> 2;  // 32 chunks * 1004 rows == VV
            int base = chunk * 1004;
            float* pp = sm;
            for (int i = tid; i < 1004; i += 256) {
#pragma unroll
                for (int b = 0; b < BB; b++) {
                    float pv = expf(g_logits[(size_t)b * VV + base + i]) * invb[b];
                    pp[b * 1004 + i] = pv;
                    if (colgrp == 0) __stcs(&outp[((size_t)b * TT + t) * VV + base + i], pv);
                }
            }
            __syncthreads();
            if (t + 1 < TT) {
                int g = tid & 31, s = tid >> 5;
                int col = (colgrp << 7) + (g << 2);
                float4 a0 = make_float4(0.f, 0.f, 0.f, 0.f), a1 = a0, a2 = a0, a3 = a0;
                for (int i = s; i < 1004; i += 8) {
                    float4 e = __ldcs((const float4*)(emb + (size_t)(base + i) * DD + col));
                    float p0 = pp[i], p1 = pp[1004 + i], p2 = pp[2008 + i], p3 = pp[3012 + i];
                    a0.x += p0 * e.x; a0.y += p0 * e.y; a0.z += p0 * e.z; a0.w += p0 * e.w;
                    a1.x += p1 * e.x; a1.y += p1 * e.y; a1.z += p1 * e.z; a1.w += p1 * e.w;
                    a2.x += p2 * e.x; a2.y += p2 * e.y; a2.z += p2 * e.z; a2.w += p2 * e.w;
                    a3.x += p3 * e.x; a3.y += p3 * e.y; a3.z += p3 * e.z; a3.w += p3 * e.w;
                }
                float4* part4 = (float4*)(sm + 4096);
                part4[tid * 4 + 0] = a0; part4[tid * 4 + 1] = a1;
                part4[tid * 4 + 2] = a2; part4[tid * 4 + 3] = a3;
                __syncthreads();
                if (tid < 128) {
                    int gg = tid & 31, b = tid >> 5;
                    float4 ts = make_float4(0.f, 0.f, 0.f, 0.f);
#pragma unroll
                    for (int s2 = 0; s2 < 8; s2++) {
                        float4 p = part4[(s2 * 32 + gg) * 4 + b];
                        ts.x += p.x; ts.y += p.y; ts.z += p.z; ts.w += p.w;
                    }
                    int co = (colgrp << 7) + (gg << 2);
                    atomicAdd(&nxt[b * DD + co + 0], ts.x);
                    atomicAdd(&nxt[b * DD + co + 1], ts.y);
                    atomicAdd(&nxt[b * DD + co + 2], ts.z);
                    atomicAdd(&nxt[b * DD + co + 3], ts.w);
                }
            }
            if (blk == 0 && tid < BB && outf) {
                unsigned idx = ~(unsigned)(g_red_key[tid] & 0xFFFFFFFFull);
                outf[tid * TT + t] = (idx == 0) ? 1.f : 0.f;
            }
        }
        gbar();
    }
}

// ============================================================================
extern "C" void kernel_launch(void* const* d_in, const int* in_sizes, int n_in,
                              void* d_out, int out_size) {
    const int*   ids  = (const int*)d_in[0];
    const float* mask = (const float*)d_in[1];
    const float* emb  = (const float*)d_in[2];
    const float* ewq  = (const float*)d_in[3];
    const float* ewk  = (const float*)d_in[4];
    const float* ewv  = (const float*)d_in[5];
    const float* ewo  = (const float*)d_in[6];
    const float* eln1 = (const float*)d_in[7];
    const float* ew1  = (const float*)d_in[8];
    const float* ew2  = (const float*)d_in[9];
    const float* eln2 = (const float*)d_in[10];
    const float* elnf = (const float*)d_in[11];
    const float* dsq  = (const float*)d_in[12];
    const float* dsk  = (const float*)d_in[13];
    const float* dsv  = (const float*)d_in[14];
    const float* dso  = (const float*)d_in[15];
    const float* dln1 = (const float*)d_in[16];
    const float* dcq  = (const float*)d_in[17];
    const float* dck  = (const float*)d_in[18];
    const float* dcv  = (const float*)d_in[19];
    const float* dco  = (const float*)d_in[20];
    const float* dln2 = (const float*)d_in[21];
    const float* dw1  = (const float*)d_in[22];
    const float* dw2  = (const float*)d_in[23];
    const float* dln3 = (const float*)d_in[24];
    const float* dlnf = (const float*)d_in[25];
    const float* lmh  = (const float*)d_in[26];

    float* outp = (float*)d_out;
    float* outf = (out_size >= BB * TT * VV + BB * TT) ? (outp + (size_t)BB * TT * VV) : nullptr;

    void* p;
    cudaGetSymbolAddress(&p, g_x);    float* px   = (float*)p;
    cudaGetSymbolAddress(&p, g_h);    float* ph   = (float*)p;
    cudaGetSymbolAddress(&p, g_qkv);  float* pqkv = (float*)p;
    cudaGetSymbolAddress(&p, g_ao);   float* pao  = (float*)p;
    cudaGetSymbolAddress(&p, g_ffn);  float* pffn = (float*)p;
    cudaGetSymbolAddress(&p, g_hs);   float* phs  = (float*)p;
    cudaGetSymbolAddress(&p, g_ckv);  float* pckv = (float*)p;

    const int M = BB * SS;   // 256
    const int MD = M * DD;   // 131072
    float* pq = pqkv;
    float* pk = pqkv + MD;
    float* pv = pqkv + 2 * MD;

    // ---------------- encoder ----------------
    k_embed<<<BB * SS, 128>>>(ids, emb, mask);
    for (int l = 0; l < LL; l++) {
        size_t o2 = (size_t)l * DD * DD;
        k_rmsnorm<<<M, 256>>>(px, eln1 + l * DD, ph, pqkv, 3 * MD);
        k_egemm3<<<dim3(8, 4, 6), 256>>>(ph, ewq + o2, ewk + o2, ewv + o2,
                                         pq, pk, pv, DD, DD, 2, 0);
        k_enc_attn5<<<BB * HH * 4, 256>>>(pq, pk, pv, pao);
        k_egemm3<<<dim3(8, 4, 4), 256>>>(pao, ewo + o2, nullptr, nullptr,
                                         px, nullptr, nullptr, DD, DD, 4, 0);
        k_rmsnorm<<<M, 256>>>(px, eln2 + l * DD, ph, pffn, M * DFF);
        k_egemm3<<<dim3(32, 4, 2), 256>>>(ph, ew1 + (size_t)l * DD * DFF, nullptr, nullptr,
                                          pffn, nullptr, nullptr, DFF, DD, 2, 0);
        k_egemm3<<<dim3(8, 4, 8), 256>>>(pffn, ew2 + (size_t)l * DFF * DD, nullptr, nullptr,
                                         px, nullptr, nullptr, DD, DFF, 8, 1);
    }
    k_rmsnorm<<<M, 256>>>(px, elnf, phs, pckv, 2 * LL * MD);
    for (int l = 0; l < LL; l++) {
        size_t o2 = (size_t)l * DD * DD;
        float* kcl = pckv + (size_t)(l * 2 + 0) * MD;
        float* vcl = pckv + (size_t)(l * 2 + 1) * MD;
        k_egemm3<<<dim3(8, 4, 4), 256>>>(phs, dck + o2, dcv + o2, nullptr,
                                         kcl, vcl, nullptr, DD, DD, 2, 0);
    }

    // ---------------- decoder: single persistent megakernel ----------------
    k_dec_init<<<(BB * DD + 255) / 256, 256>>>(emb);
    k_decode<<<NBLK, 256>>>(dsq, dsk, dsv, dso, dln1, dcq, dco, dln2,
                            dw1, dw2, dln3, dlnf, lmh, emb, outp, outf);
}